// round 16
// baseline (speedup 1.0000x reference)
#include <cuda_runtime.h>
#include <cuda_fp16.h>
#include <cstdint>
#include <math.h>

#define T_TOK 2048
#define D_DIM 1024
#define F_DIM 2048
#define NE 8

// ---- scratch: referenced ONLY inside device code ----
__device__ __half g_sWg16[(size_t)D_DIM * F_DIM];
__device__ __half g_sWu16[(size_t)D_DIM * F_DIM];
__device__ __half g_sWd16[(size_t)F_DIM * D_DIM];
__device__ __half g_X16 [(size_t)T_TOK * D_DIM];   // hidden fp16 (token order)
__device__ __half g_Xe16[(size_t)T_TOK * D_DIM];   // scaled fp16 (grouped order)
__device__ __half g_H16 [(size_t)T_TOK * F_DIM];   // shared H fp16
__device__ __half g_H216[(size_t)T_TOK * F_DIM];   // routed H fp16
__device__ float g_O2[(size_t)T_TOK * D_DIM];
__device__ int   g_tok_e[T_TOK];
__device__ float g_tok_s[T_TOK];
__device__ int   g_row[T_TOK];
__device__ int   g_order[T_TOK];
__device__ int   g_offs[NE + 1];

__device__ __forceinline__ float silu_f(float x) { return x / (1.0f + expf(-x)); }

__device__ __forceinline__ unsigned cvt2(float x0, float x1) {
    return (unsigned)__half_as_ushort(__float2half_rn(x0))
         | ((unsigned)__half_as_ushort(__float2half_rn(x1)) << 16);
}

__device__ __forceinline__ void cpa16(void* smem, const void* gmem) {
    unsigned s = (unsigned)__cvta_generic_to_shared(smem);
    asm volatile("cp.async.cg.shared.global [%0], [%1], 16;" :: "r"(s), "l"(gmem));
}
__device__ __forceinline__ void cpa_commit() { asm volatile("cp.async.commit_group;"); }
__device__ __forceinline__ void cpa_wait_all() { asm volatile("cp.async.wait_group 0;" ::: "memory"); }

__device__ __forceinline__ void ldsm4(unsigned r[4], const void* p) {
    unsigned a = (unsigned)__cvta_generic_to_shared(p);
    asm volatile("ldmatrix.sync.aligned.m8n8.x4.shared.b16 {%0,%1,%2,%3}, [%4];"
                 : "=r"(r[0]), "=r"(r[1]), "=r"(r[2]), "=r"(r[3]) : "r"(a));
}
__device__ __forceinline__ void ldsm4t(unsigned r[4], const void* p) {
    unsigned a = (unsigned)__cvta_generic_to_shared(p);
    asm volatile("ldmatrix.sync.aligned.m8n8.x4.trans.shared.b16 {%0,%1,%2,%3}, [%4];"
                 : "=r"(r[0]), "=r"(r[1]), "=r"(r[2]), "=r"(r[3]) : "r"(a));
}
__device__ __forceinline__ void mma_f16(float c[4], const unsigned a[4], unsigned b0, unsigned b1) {
    asm volatile(
        "mma.sync.aligned.m16n8k16.row.col.f32.f16.f16.f32 "
        "{%0,%1,%2,%3}, {%4,%5,%6,%7}, {%8,%9}, {%0,%1,%2,%3};"
        : "+f"(c[0]), "+f"(c[1]), "+f"(c[2]), "+f"(c[3])
        : "r"(a[0]), "r"(a[1]), "r"(a[2]), "r"(a[3]), "r"(b0), "r"(b1));
}

// ---------------- convert shared weights ----------------
__global__ void conv_shared(const float* __restrict__ g, const float* __restrict__ u,
                            const float* __restrict__ d) {
    const int n4 = D_DIM * F_DIM / 4;
    for (int idx = blockIdx.x * 256 + threadIdx.x; idx < 3 * n4; idx += gridDim.x * 256) {
        int which = idx / n4, i = idx - which * n4;
        const float* src = (which == 0) ? g : (which == 1) ? u : d;
        __half* dst = (which == 0) ? g_sWg16 : (which == 1) ? g_sWu16 : g_sWd16;
        float4 v = ((const float4*)src)[i];
        ((unsigned*)dst)[2 * i]     = cvt2(v.x, v.y);
        ((unsigned*)dst)[2 * i + 1] = cvt2(v.z, v.w);
    }
}

// ---------------- router ----------------
__global__ void router_kernel(const float* __restrict__ x, const float* __restrict__ rw) {
    __shared__ float red[256][NE + 1];
    int t = blockIdx.x, tid = threadIdx.x;
    float4 xa = ((const float4*)(x + (size_t)t * D_DIM))[tid];
#pragma unroll
    for (int e = 0; e < NE; e++) {
        float4 wv = ((const float4*)(rw + (size_t)e * D_DIM))[tid];
        red[tid][e] = xa.x * wv.x + xa.y * wv.y + xa.z * wv.z + xa.w * wv.w;
    }
    __syncthreads();
    for (int s = 128; s > 0; s >>= 1) {
        if (tid < s)
#pragma unroll
            for (int e = 0; e < NE; e++) red[tid][e] += red[tid + s][e];
        __syncthreads();
    }
    if (tid == 0) {
        float bv = red[0][0]; int be = 0;
#pragma unroll
        for (int e = 1; e < NE; e++) if (red[0][e] > bv) { bv = red[0][e]; be = e; }
        g_tok_e[t] = be;
        g_tok_s[t] = 1.0f / (1.0f + expf(-bv));
    }
}

// ---------------- stable rank + offsets ----------------
__global__ void rank_kernel() {
    __shared__ int s_e[T_TOK];
    int tid = threadIdx.x;
    for (int i = tid; i < T_TOK; i += 256) s_e[i] = g_tok_e[i];
    __syncthreads();
    int t = blockIdx.x * 256 + tid;
    int e = s_e[t];
    int r = 0;
#pragma unroll 4
    for (int u = 0; u < T_TOK; u++) {
        int eu = s_e[u];
        r += (eu < e) || (eu == e && u < t);
    }
    g_row[t] = r;
    g_order[r] = t;
    if (blockIdx.x == 0 && tid <= NE) {
        int c = 0;
#pragma unroll 4
        for (int u = 0; u < T_TOK; u++) c += (s_e[u] < tid);
        g_offs[tid] = c;
    }
}

// ---------------- scatter+convert hidden ----------------
__global__ void scatter_convert(const float* __restrict__ x) {
    int t = blockIdx.x, tid = threadIdx.x;
    int r = g_row[t];
    float s = g_tok_s[t];
    float4 v = ((const float4*)(x + (size_t)t * D_DIM))[tid];
    size_t o = ((size_t)t * D_DIM) / 2 + tid * 2;
    ((unsigned*)g_X16)[o]     = cvt2(v.x, v.y);
    ((unsigned*)g_X16)[o + 1] = cvt2(v.z, v.w);
    size_t o2 = ((size_t)r * D_DIM) / 2 + tid * 2;
    ((unsigned*)g_Xe16)[o2]     = cvt2(v.x * s, v.y * s);
    ((unsigned*)g_Xe16)[o2 + 1] = cvt2(v.z * s, v.w * s);
}

// ================= gate+up GEMM: BK=64, 2-stage, pure fp16 =================
// per-stage (bytes): A@0 (18432 = 128*72*2), G@18432 (9216 = 64*72*2), U@27648 -> 36864/stage
#define GU_STG 36864
#define GU_SMEM_BYTES (2 * GU_STG)
#define GU_LDA 72
#define GU_LDB 72

__global__ void __launch_bounds__(256, 2)
gemm_gateup_all(const float* __restrict__ w_gate, const float* __restrict__ w_up) {
    const int BK = 64;
    const int K = D_DIM, N = F_DIM;
    extern __shared__ __align__(16) char dsm[];

    int z = blockIdx.z;
    bool routed = (z > 0);
    int e = z - 1;
    int seg_start = 0, seg_rows = T_TOK;
    const __half *A16;
    __half *H16;
    const float *Gf = nullptr, *Uf = nullptr;
    const __half *Gp = nullptr, *Upp = nullptr;
    if (routed) {
        seg_start = g_offs[e]; seg_rows = g_offs[e + 1] - seg_start;
        A16 = g_Xe16;
        Gf = w_gate + (size_t)e * D_DIM * F_DIM;
        Uf = w_up   + (size_t)e * D_DIM * F_DIM;
        H16 = g_H216;
    } else {
        A16 = g_X16;
        Gp = g_sWg16; Upp = g_sWu16;
        H16 = g_H16;
    }
    int row0 = blockIdx.y * 128;
    if (row0 >= seg_rows) return;
    int col0 = blockIdx.x * 64;

    int tid = threadIdx.x, lane = tid & 31, wid = tid >> 5;
    int wm = wid & 3, wn = wid >> 2;

    auto pA = [&](int buf) { return (__half*)(dsm + buf * GU_STG); };
    auto pG = [&](int buf) { return (__half*)(dsm + buf * GU_STG + 18432); };
    auto pU = [&](int buf) { return (__half*)(dsm + buf * GU_STG + 27648); };

    // A staging: 128 rows x 8 chunks = 1024 slots -> 4/thread
    int ar[4], ac[4]; const __half* ap[4];
#pragma unroll
    for (int i = 0; i < 4; i++) {
        int idx = i * 256 + tid;
        ar[i] = idx >> 3; ac[i] = (idx & 7) * 8;
        int rg = row0 + ar[i]; if (rg >= seg_rows) rg = 0;   // clamp; discarded in epilogue
        ap[i] = A16 + (size_t)(seg_start + rg) * K + ac[i];
    }
    // B shared path: 2 matrices x 512 slots (64 rows x 8 chunks); half-block per matrix, 4 slots each
    int bplq = tid >> 7, bsub = tid & 127;
    int br[4], bc[4]; const __half* bps[4] = { nullptr, nullptr, nullptr, nullptr };
#pragma unroll
    for (int i = 0; i < 4; i++) {
        int idx = i * 128 + bsub;
        br[i] = idx >> 3; bc[i] = (idx & 7) * 8;
        if (!routed) bps[i] = (bplq ? Upp : Gp) + (size_t)br[i] * N + col0 + bc[i];
    }
    // B routed path: 1024 float4 per matrix -> 4/thread/matrix; group i = k-rows [16i,16i+16)
    int bkr[4], bcc[4]; const float *gp[4] = {}, *up[4] = {};
#pragma unroll
    for (int i = 0; i < 4; i++) {
        int idx = i * 256 + tid;
        bkr[i] = idx >> 4; bcc[i] = (idx & 15) * 4;
        if (routed) {
            gp[i] = Gf + (size_t)bkr[i] * N + col0 + bcc[i];
            up[i] = Uf + (size_t)bkr[i] * N + col0 + bcc[i];
        }
    }

    float accg[2][4][4] = {}, accu[2][4][4] = {};

    auto stage_async = [&](int buf, int tile) {
        __half* sA = pA(buf);
#pragma unroll
        for (int i = 0; i < 4; i++)
            cpa16(sA + ar[i] * GU_LDA + ac[i], ap[i] + tile * BK);
        if (!routed) {
            __half* sB = bplq ? pU(buf) : pG(buf);
#pragma unroll
            for (int i = 0; i < 4; i++)
                cpa16(sB + br[i] * GU_LDB + bc[i], bps[i] + (size_t)tile * BK * N);
        }
        cpa_commit();
    };
    auto store_routedB1 = [&](int buf, int i, float4 gv, float4 uv) {
        __half* sG = pG(buf); __half* sU = pU(buf);
        int off = bkr[i] * GU_LDB + bcc[i];
        *(unsigned*)&sG[off]     = cvt2(gv.x, gv.y);
        *(unsigned*)&sG[off + 2] = cvt2(gv.z, gv.w);
        *(unsigned*)&sU[off]     = cvt2(uv.x, uv.y);
        *(unsigned*)&sU[off + 2] = cvt2(uv.z, uv.w);
    };

    auto compute_kh = [&](int buf, int kh) {
        const __half* sA = pA(buf);
        const __half* sG = pG(buf);
        const __half* sU = pU(buf);
        unsigned a[2][4];
#pragma unroll
        for (int mt = 0; mt < 2; mt++) {
            int r = wm * 32 + mt * 16 + (lane & 15);
            int kk = kh * 16 + (lane >> 4) * 8;
            ldsm4(a[mt], sA + r * GU_LDA + kk);
        }
#pragma unroll
        for (int h = 0; h < 2; h++) {
            int krow = kh * 16 + (lane & 15);
            int nof = wn * 32 + h * 16 + (lane >> 4) * 8;
            unsigned gg[4], uu[4];
            ldsm4t(gg, sG + krow * GU_LDB + nof);
            ldsm4t(uu, sU + krow * GU_LDB + nof);
#pragma unroll
            for (int mt = 0; mt < 2; mt++)
#pragma unroll
                for (int nn = 0; nn < 2; nn++) {
                    mma_f16(accg[mt][h * 2 + nn], a[mt], gg[2*nn], gg[2*nn+1]);
                    mma_f16(accu[mt][h * 2 + nn], a[mt], uu[2*nn], uu[2*nn+1]);
                }
        }
    };

    const int nC = K / BK;   // 16
    stage_async(0, 0);
    if (routed) {
#pragma unroll
        for (int i = 0; i < 4; i++)
            store_routedB1(0, i, *(const float4*)gp[i], *(const float4*)up[i]);
    }
    cpa_wait_all();
    __syncthreads();

    for (int t = 0; t < nC; t++) {
        int buf = t & 1;
        bool more = (t + 1) < nC;
        if (more) stage_async(buf ^ 1, t + 1);
#pragma unroll
        for (int kh = 0; kh < 4; kh++) {
            float4 gv, uv;
            if (more && routed) {
                gv = *(const float4*)(gp[kh] + (size_t)(t + 1) * BK * N);
                uv = *(const float4*)(up[kh] + (size_t)(t + 1) * BK * N);
            }
            compute_kh(buf, kh);
            if (more && routed) store_routedB1(buf ^ 1, kh, gv, uv);
        }
        if (more) cpa_wait_all();
        __syncthreads();
    }

    __half* Hs = H16 + (size_t)seg_start * N;
#pragma unroll
    for (int mt = 0; mt < 2; mt++)
#pragma unroll
        for (int nn = 0; nn < 4; nn++) {
            int r0 = row0 + wm * 32 + mt * 16 + (lane >> 2);
            int c = col0 + wn * 32 + nn * 8 + (lane & 3) * 2;
            float* cg = accg[mt][nn]; float* cu = accu[mt][nn];
            if (r0 < seg_rows)
                ((unsigned*)Hs)[((size_t)r0 * N + c) >> 1] =
                    cvt2(silu_f(cg[0]) * cu[0], silu_f(cg[1]) * cu[1]);
            int r1 = r0 + 8;
            if (r1 < seg_rows)
                ((unsigned*)Hs)[((size_t)r1 * N + c) >> 1] =
                    cvt2(silu_f(cg[2]) * cu[2], silu_f(cg[3]) * cu[3]);
        }
}

// ================= down GEMM: BK=64, 2-stage, pure fp16 =================
// per-stage: A@0 (18432), B@18432 (17408 = 64*136*2) -> 35840/stage
#define DN_STG 35840
#define DN_SMEM_BYTES (2 * DN_STG)
#define DN_LDA 72
#define DN_LDB 136

__global__ void __launch_bounds__(256, 2)
gemm_down_all(float* __restrict__ out, const float* __restrict__ w_down) {
    const int BK = 64;
    const int K = F_DIM, N = D_DIM;
    extern __shared__ __align__(16) char dsm[];

    int z = blockIdx.z;
    bool routed = (z > 0);
    int e = z - 1;
    int seg_start = 0, seg_rows = T_TOK;
    const __half *A16, *Bp = nullptr;
    const float* Bf = nullptr;
    if (routed) {
        seg_start = g_offs[e]; seg_rows = g_offs[e + 1] - seg_start;
        A16 = g_H216;
        Bf = w_down + (size_t)e * F_DIM * D_DIM;
    } else {
        A16 = g_H16; Bp = g_sWd16;
    }
    int row0 = blockIdx.y * 128;
    if (row0 >= seg_rows) return;
    int col0 = blockIdx.x * 128;

    int tid = threadIdx.x, lane = tid & 31, wid = tid >> 5;
    int wm = wid & 3, wn = wid >> 2;

    auto pA = [&](int buf) { return (__half*)(dsm + buf * DN_STG); };
    auto pB = [&](int buf) { return (__half*)(dsm + buf * DN_STG + 18432); };

    int ar[4], ac[4]; const __half* ap[4];
#pragma unroll
    for (int i = 0; i < 4; i++) {
        int idx = i * 256 + tid;
        ar[i] = idx >> 3; ac[i] = (idx & 7) * 8;
        int rg = row0 + ar[i]; if (rg >= seg_rows) rg = 0;
        ap[i] = A16 + (size_t)(seg_start + rg) * K + ac[i];
    }
    // shared B: 64 rows x 16 chunks = 1024 slots -> 4/thread
    int br[4], bc[4]; const __half* bps[4] = { nullptr, nullptr, nullptr, nullptr };
#pragma unroll
    for (int i = 0; i < 4; i++) {
        int idx = i * 256 + tid;
        br[i] = idx >> 4; bc[i] = (idx & 15) * 8;
        if (!routed) bps[i] = Bp + (size_t)br[i] * N + col0 + bc[i];
    }
    // routed B fp32: 2048 float4 -> 8/thread; group kh: slots [kh*512, kh*512+512) = k-rows [16kh,16kh+16)
    int bkr[8], bcc[8]; const float* bp[8] = {};
#pragma unroll
    for (int i = 0; i < 8; i++) {
        int idx = i * 256 + tid;
        bkr[i] = idx >> 5; bcc[i] = (idx & 31) * 4;
        if (routed) bp[i] = Bf + (size_t)bkr[i] * N + col0 + bcc[i];
    }

    float acc[2][8][4] = {};

    auto stage_async = [&](int buf, int tile) {
        __half* sA = pA(buf);
#pragma unroll
        for (int i = 0; i < 4; i++)
            cpa16(sA + ar[i] * DN_LDA + ac[i], ap[i] + tile * BK);
        if (!routed) {
            __half* sB = pB(buf);
#pragma unroll
            for (int i = 0; i < 4; i++)
                cpa16(sB + br[i] * DN_LDB + bc[i], bps[i] + (size_t)tile * BK * N);
        }
        cpa_commit();
    };
    auto store_routedB1 = [&](int buf, int i, float4 bv) {
        __half* sB = pB(buf);
        int off = bkr[i] * DN_LDB + bcc[i];
        *(unsigned*)&sB[off]     = cvt2(bv.x, bv.y);
        *(unsigned*)&sB[off + 2] = cvt2(bv.z, bv.w);
    };

    auto compute_kh = [&](int buf, int kh) {
        const __half* sA = pA(buf);
        const __half* sB = pB(buf);
        unsigned a[2][4];
#pragma unroll
        for (int mt = 0; mt < 2; mt++) {
            int r = wm * 32 + mt * 16 + (lane & 15);
            int kk = kh * 16 + (lane >> 4) * 8;
            ldsm4(a[mt], sA + r * DN_LDA + kk);
        }
#pragma unroll
        for (int h = 0; h < 4; h++) {
            int krow = kh * 16 + (lane & 15);
            int nof = wn * 64 + h * 16 + (lane >> 4) * 8;
            unsigned bb[4];
            ldsm4t(bb, sB + krow * DN_LDB + nof);
#pragma unroll
            for (int mt = 0; mt < 2; mt++)
#pragma unroll
                for (int nn = 0; nn < 2; nn++)
                    mma_f16(acc[mt][h * 2 + nn], a[mt], bb[2*nn], bb[2*nn+1]);
        }
    };

    const int nC = K / BK;   // 32
    stage_async(0, 0);
    if (routed) {
#pragma unroll
        for (int i = 0; i < 8; i++)
            store_routedB1(0, i, *(const float4*)bp[i]);
    }
    cpa_wait_all();
    __syncthreads();

    for (int t = 0; t < nC; t++) {
        int buf = t & 1;
        bool more = (t + 1) < nC;
        if (more) stage_async(buf ^ 1, t + 1);
#pragma unroll
        for (int kh = 0; kh < 4; kh++) {
            float4 bv0, bv1;
            if (more && routed) {
                bv0 = *(const float4*)(bp[kh * 2]     + (size_t)(t + 1) * BK * N);
                bv1 = *(const float4*)(bp[kh * 2 + 1] + (size_t)(t + 1) * BK * N);
            }
            compute_kh(buf, kh);
            if (more && routed) {
                store_routedB1(buf ^ 1, kh * 2,     bv0);
                store_routedB1(buf ^ 1, kh * 2 + 1, bv1);
            }
        }
        if (more) cpa_wait_all();
        __syncthreads();
    }

#pragma unroll
    for (int mt = 0; mt < 2; mt++) {
        int rb0 = row0 + wm * 32 + mt * 16 + (lane >> 2);
        int rb1 = rb0 + 8;
        int tok0 = -1, tok1 = -1;
        if (rb0 < seg_rows) tok0 = routed ? g_order[seg_start + rb0] : rb0;
        if (rb1 < seg_rows) tok1 = routed ? g_order[seg_start + rb1] : rb1;
        float* dst = routed ? g_O2 : out;
#pragma unroll
        for (int nn = 0; nn < 8; nn++) {
            int c = col0 + wn * 64 + nn * 8 + (lane & 3) * 2;
            float* cc = acc[mt][nn];
            if (tok0 >= 0) { float2 v = { cc[0], cc[1] }; *(float2*)&dst[(size_t)tok0 * N + c] = v; }
            if (tok1 >= 0) { float2 v = { cc[2], cc[3] }; *(float2*)&dst[(size_t)tok1 * N + c] = v; }
        }
    }
}

// ---------------- final add ----------------
__global__ void add_kernel(float* __restrict__ out) {
    size_t i = (size_t)blockIdx.x * 256 + threadIdx.x;
    float4 v = ((float4*)out)[i];
    float4 w = ((const float4*)g_O2)[i];
    v.x += w.x; v.y += w.y; v.z += w.z; v.w += w.w;
    ((float4*)out)[i] = v;
}

extern "C" void kernel_launch(void* const* d_in, const int* in_sizes, int n_in,
                              void* d_out, int out_size) {
    const float* hidden   = (const float*)d_in[0];
    const float* router_w = (const float*)d_in[1];
    const float* w_gate   = (const float*)d_in[2];
    const float* w_up     = (const float*)d_in[3];
    const float* w_down   = (const float*)d_in[4];
    const float* ws_gate  = (const float*)d_in[5];
    const float* ws_up    = (const float*)d_in[6];
    const float* ws_down  = (const float*)d_in[7];
    float* out = (float*)d_out;

    cudaFuncSetAttribute(gemm_gateup_all, cudaFuncAttributeMaxDynamicSharedMemorySize, GU_SMEM_BYTES);
    cudaFuncSetAttribute(gemm_down_all,   cudaFuncAttributeMaxDynamicSharedMemorySize, DN_SMEM_BYTES);

    conv_shared<<<512, 256>>>(ws_gate, ws_up, ws_down);
    router_kernel<<<T_TOK, 256>>>(hidden, router_w);
    rank_kernel<<<T_TOK / 256, 256>>>();
    scatter_convert<<<T_TOK, 256>>>(hidden);

    dim3 gridGU(F_DIM / 64, T_TOK / 128, NE + 1);
    gemm_gateup_all<<<gridGU, 256, GU_SMEM_BYTES>>>(w_gate, w_up);
    dim3 gridDN(D_DIM / 128, T_TOK / 128, NE + 1);
    gemm_down_all<<<gridDN, 256, DN_SMEM_BYTES>>>(out, w_down);
    add_kernel<<<(T_TOK * D_DIM / 4) / 256, 256>>>(out);

    (void)in_sizes; (void)n_in; (void)out_size;
}

// round 17
// speedup vs baseline: 1.1004x; 1.1004x over previous
#include <cuda_runtime.h>
#include <cuda_fp16.h>
#include <cstdint>
#include <math.h>

#define T_TOK 2048
#define D_DIM 1024
#define F_DIM 2048
#define NE 8

// ---- scratch: referenced ONLY inside device code ----
__device__ __half g_sWg16[(size_t)D_DIM * F_DIM];
__device__ __half g_sWu16[(size_t)D_DIM * F_DIM];
__device__ __half g_sWd16[(size_t)F_DIM * D_DIM];
__device__ __half g_X16 [(size_t)T_TOK * D_DIM];   // hidden fp16 (token order)
__device__ __half g_Xe16[(size_t)T_TOK * D_DIM];   // scaled fp16 (grouped order)
__device__ __half g_H16 [(size_t)T_TOK * F_DIM];   // shared H fp16
__device__ __half g_H216[(size_t)T_TOK * F_DIM];   // routed H fp16
__device__ float g_P[(size_t)4 * T_TOK * D_DIM];   // down partials: [kz*2 + routed][T,D]
__device__ int   g_tok_e[T_TOK];
__device__ float g_tok_s[T_TOK];
__device__ int   g_row[T_TOK];
__device__ int   g_order[T_TOK];
__device__ int   g_offs[NE + 1];

__device__ __forceinline__ float silu_f(float x) { return x / (1.0f + expf(-x)); }

__device__ __forceinline__ unsigned cvt2(float x0, float x1) {
    return (unsigned)__half_as_ushort(__float2half_rn(x0))
         | ((unsigned)__half_as_ushort(__float2half_rn(x1)) << 16);
}

__device__ __forceinline__ void cpa16(void* smem, const void* gmem) {
    unsigned s = (unsigned)__cvta_generic_to_shared(smem);
    asm volatile("cp.async.cg.shared.global [%0], [%1], 16;" :: "r"(s), "l"(gmem));
}
__device__ __forceinline__ void cpa_commit() { asm volatile("cp.async.commit_group;"); }
__device__ __forceinline__ void cpa_wait_all() { asm volatile("cp.async.wait_group 0;" ::: "memory"); }

__device__ __forceinline__ void ldsm4(unsigned r[4], const void* p) {
    unsigned a = (unsigned)__cvta_generic_to_shared(p);
    asm volatile("ldmatrix.sync.aligned.m8n8.x4.shared.b16 {%0,%1,%2,%3}, [%4];"
                 : "=r"(r[0]), "=r"(r[1]), "=r"(r[2]), "=r"(r[3]) : "r"(a));
}
__device__ __forceinline__ void ldsm4t(unsigned r[4], const void* p) {
    unsigned a = (unsigned)__cvta_generic_to_shared(p);
    asm volatile("ldmatrix.sync.aligned.m8n8.x4.trans.shared.b16 {%0,%1,%2,%3}, [%4];"
                 : "=r"(r[0]), "=r"(r[1]), "=r"(r[2]), "=r"(r[3]) : "r"(a));
}
__device__ __forceinline__ void mma_f16(float c[4], const unsigned a[4], unsigned b0, unsigned b1) {
    asm volatile(
        "mma.sync.aligned.m16n8k16.row.col.f32.f16.f16.f32 "
        "{%0,%1,%2,%3}, {%4,%5,%6,%7}, {%8,%9}, {%0,%1,%2,%3};"
        : "+f"(c[0]), "+f"(c[1]), "+f"(c[2]), "+f"(c[3])
        : "r"(a[0]), "r"(a[1]), "r"(a[2]), "r"(a[3]), "r"(b0), "r"(b1));
}

// ---------------- convert shared weights ----------------
__global__ void conv_shared(const float* __restrict__ g, const float* __restrict__ u,
                            const float* __restrict__ d) {
    const int n4 = D_DIM * F_DIM / 4;
    for (int idx = blockIdx.x * 256 + threadIdx.x; idx < 3 * n4; idx += gridDim.x * 256) {
        int which = idx / n4, i = idx - which * n4;
        const float* src = (which == 0) ? g : (which == 1) ? u : d;
        __half* dst = (which == 0) ? g_sWg16 : (which == 1) ? g_sWu16 : g_sWd16;
        float4 v = ((const float4*)src)[i];
        ((unsigned*)dst)[2 * i]     = cvt2(v.x, v.y);
        ((unsigned*)dst)[2 * i + 1] = cvt2(v.z, v.w);
    }
}

// ---------------- router ----------------
__global__ void router_kernel(const float* __restrict__ x, const float* __restrict__ rw) {
    __shared__ float red[256][NE + 1];
    int t = blockIdx.x, tid = threadIdx.x;
    float4 xa = ((const float4*)(x + (size_t)t * D_DIM))[tid];
#pragma unroll
    for (int e = 0; e < NE; e++) {
        float4 wv = ((const float4*)(rw + (size_t)e * D_DIM))[tid];
        red[tid][e] = xa.x * wv.x + xa.y * wv.y + xa.z * wv.z + xa.w * wv.w;
    }
    __syncthreads();
    for (int s = 128; s > 0; s >>= 1) {
        if (tid < s)
#pragma unroll
            for (int e = 0; e < NE; e++) red[tid][e] += red[tid + s][e];
        __syncthreads();
    }
    if (tid == 0) {
        float bv = red[0][0]; int be = 0;
#pragma unroll
        for (int e = 1; e < NE; e++) if (red[0][e] > bv) { bv = red[0][e]; be = e; }
        g_tok_e[t] = be;
        g_tok_s[t] = 1.0f / (1.0f + expf(-bv));
    }
}

// ---------------- stable rank + offsets ----------------
__global__ void rank_kernel() {
    __shared__ int s_e[T_TOK];
    int tid = threadIdx.x;
    for (int i = tid; i < T_TOK; i += 256) s_e[i] = g_tok_e[i];
    __syncthreads();
    int t = blockIdx.x * 256 + tid;
    int e = s_e[t];
    int r = 0;
#pragma unroll 4
    for (int u = 0; u < T_TOK; u++) {
        int eu = s_e[u];
        r += (eu < e) || (eu == e && u < t);
    }
    g_row[t] = r;
    g_order[r] = t;
    if (blockIdx.x == 0 && tid <= NE) {
        int c = 0;
#pragma unroll 4
        for (int u = 0; u < T_TOK; u++) c += (s_e[u] < tid);
        g_offs[tid] = c;
    }
}

// ---------------- scatter+convert hidden ----------------
__global__ void scatter_convert(const float* __restrict__ x) {
    int t = blockIdx.x, tid = threadIdx.x;
    int r = g_row[t];
    float s = g_tok_s[t];
    float4 v = ((const float4*)(x + (size_t)t * D_DIM))[tid];
    size_t o = ((size_t)t * D_DIM) / 2 + tid * 2;
    ((unsigned*)g_X16)[o]     = cvt2(v.x, v.y);
    ((unsigned*)g_X16)[o + 1] = cvt2(v.z, v.w);
    size_t o2 = ((size_t)r * D_DIM) / 2 + tid * 2;
    ((unsigned*)g_Xe16)[o2]     = cvt2(v.x * s, v.y * s);
    ((unsigned*)g_Xe16)[o2 + 1] = cvt2(v.z * s, v.w * s);
}

// ================= gate+up GEMM: BK=32, 2-stage, pure fp16 (R15, unchanged) =================
#define GU_STG 19456
#define GU_SMEM_BYTES (2 * GU_STG)
#define GU_LDA 40
#define GU_LDB 72

__global__ void __launch_bounds__(256, 2)
gemm_gateup_all(const float* __restrict__ w_gate, const float* __restrict__ w_up) {
    const int BK = 32;
    const int K = D_DIM, N = F_DIM;
    extern __shared__ __align__(16) char dsm[];

    int z = blockIdx.z;
    bool routed = (z > 0);
    int e = z - 1;
    int seg_start = 0, seg_rows = T_TOK;
    const __half *A16;
    __half *H16;
    const float *Gf = nullptr, *Uf = nullptr;
    const __half *Gp = nullptr, *Upp = nullptr;
    if (routed) {
        seg_start = g_offs[e]; seg_rows = g_offs[e + 1] - seg_start;
        A16 = g_Xe16;
        Gf = w_gate + (size_t)e * D_DIM * F_DIM;
        Uf = w_up   + (size_t)e * D_DIM * F_DIM;
        H16 = g_H216;
    } else {
        A16 = g_X16;
        Gp = g_sWg16; Upp = g_sWu16;
        H16 = g_H16;
    }
    int row0 = blockIdx.y * 128;
    if (row0 >= seg_rows) return;
    int col0 = blockIdx.x * 64;

    int tid = threadIdx.x, lane = tid & 31, wid = tid >> 5;
    int wm = wid & 3, wn = wid >> 2;

    auto pA = [&](int buf) { return (__half*)(dsm + buf * GU_STG); };
    auto pG = [&](int buf) { return (__half*)(dsm + buf * GU_STG + 10240); };
    auto pU = [&](int buf) { return (__half*)(dsm + buf * GU_STG + 14848); };

    int ar[2], ac[2]; const __half* ap[2];
#pragma unroll
    for (int i = 0; i < 2; i++) {
        int idx = i * 256 + tid;
        ar[i] = idx >> 2; ac[i] = (idx & 3) * 8;
        int rg = row0 + ar[i]; if (rg >= seg_rows) rg = 0;
        ap[i] = A16 + (size_t)(seg_start + rg) * K + ac[i];
    }
    int bplq = tid >> 7, bsub = tid & 127;
    int br[2], bc[2]; const __half* bps[2] = { nullptr, nullptr };
#pragma unroll
    for (int i = 0; i < 2; i++) {
        int idx = i * 128 + bsub;
        br[i] = idx >> 3; bc[i] = (idx & 7) * 8;
        if (!routed) bps[i] = (bplq ? Upp : Gp) + (size_t)br[i] * N + col0 + bc[i];
    }
    int bkr[2], bcc[2]; const float *gp[2] = { nullptr, nullptr }, *up[2] = { nullptr, nullptr };
#pragma unroll
    for (int i = 0; i < 2; i++) {
        int idx = i * 256 + tid;
        bkr[i] = idx >> 4; bcc[i] = (idx & 15) * 4;
        if (routed) {
            gp[i] = Gf + (size_t)bkr[i] * N + col0 + bcc[i];
            up[i] = Uf + (size_t)bkr[i] * N + col0 + bcc[i];
        }
    }

    float accg[2][4][4] = {}, accu[2][4][4] = {};

    auto stage_async = [&](int buf, int tile) {
        __half* sA = pA(buf);
#pragma unroll
        for (int i = 0; i < 2; i++)
            cpa16(sA + ar[i] * GU_LDA + ac[i], ap[i] + tile * BK);
        if (!routed) {
            __half* sB = bplq ? pU(buf) : pG(buf);
#pragma unroll
            for (int i = 0; i < 2; i++)
                cpa16(sB + br[i] * GU_LDB + bc[i], bps[i] + (size_t)tile * BK * N);
        }
        cpa_commit();
    };
    auto store_routedB = [&](int buf, const float4 gv[2], const float4 uv[2]) {
        __half* sG = pG(buf); __half* sU = pU(buf);
#pragma unroll
        for (int i = 0; i < 2; i++) {
            int off = bkr[i] * GU_LDB + bcc[i];
            *(unsigned*)&sG[off]     = cvt2(gv[i].x, gv[i].y);
            *(unsigned*)&sG[off + 2] = cvt2(gv[i].z, gv[i].w);
            *(unsigned*)&sU[off]     = cvt2(uv[i].x, uv[i].y);
            *(unsigned*)&sU[off + 2] = cvt2(uv[i].z, uv[i].w);
        }
    };

    auto compute = [&](int buf) {
        const __half* sA = pA(buf);
        const __half* sG = pG(buf);
        const __half* sU = pU(buf);
#pragma unroll
        for (int kh = 0; kh < 2; kh++) {
            unsigned a[2][4];
#pragma unroll
            for (int mt = 0; mt < 2; mt++) {
                int r = wm * 32 + mt * 16 + (lane & 15);
                int kk = kh * 16 + (lane >> 4) * 8;
                ldsm4(a[mt], sA + r * GU_LDA + kk);
            }
#pragma unroll
            for (int h = 0; h < 2; h++) {
                int krow = kh * 16 + (lane & 15);
                int nof = wn * 32 + h * 16 + (lane >> 4) * 8;
                unsigned gg[4], uu[4];
                ldsm4t(gg, sG + krow * GU_LDB + nof);
                ldsm4t(uu, sU + krow * GU_LDB + nof);
#pragma unroll
                for (int mt = 0; mt < 2; mt++)
#pragma unroll
                    for (int nn = 0; nn < 2; nn++) {
                        mma_f16(accg[mt][h * 2 + nn], a[mt], gg[2*nn], gg[2*nn+1]);
                        mma_f16(accu[mt][h * 2 + nn], a[mt], uu[2*nn], uu[2*nn+1]);
                    }
            }
        }
    };

    const int nC = K / BK;   // 32
    stage_async(0, 0);
    if (routed) {
        float4 gv[2] = { *(const float4*)gp[0], *(const float4*)gp[1] };
        float4 uv[2] = { *(const float4*)up[0], *(const float4*)up[1] };
        store_routedB(0, gv, uv);
    }
    cpa_wait_all();
    __syncthreads();

    for (int t = 0; t < nC; t++) {
        int buf = t & 1;
        bool more = (t + 1) < nC;
        float4 gv[2], uv[2];
        if (more) {
            stage_async(buf ^ 1, t + 1);
            if (routed) {
#pragma unroll
                for (int i = 0; i < 2; i++) {
                    gv[i] = *(const float4*)(gp[i] + (size_t)(t + 1) * BK * N);
                    uv[i] = *(const float4*)(up[i] + (size_t)(t + 1) * BK * N);
                }
            }
        }
        compute(buf);
        if (more) {
            if (routed) store_routedB(buf ^ 1, gv, uv);
            cpa_wait_all();
        }
        __syncthreads();
    }

    __half* Hs = H16 + (size_t)seg_start * N;
#pragma unroll
    for (int mt = 0; mt < 2; mt++)
#pragma unroll
        for (int nn = 0; nn < 4; nn++) {
            int r0 = row0 + wm * 32 + mt * 16 + (lane >> 2);
            int c = col0 + wn * 32 + nn * 8 + (lane & 3) * 2;
            float* cg = accg[mt][nn]; float* cu = accu[mt][nn];
            if (r0 < seg_rows)
                ((unsigned*)Hs)[((size_t)r0 * N + c) >> 1] =
                    cvt2(silu_f(cg[0]) * cu[0], silu_f(cg[1]) * cu[1]);
            int r1 = r0 + 8;
            if (r1 < seg_rows)
                ((unsigned*)Hs)[((size_t)r1 * N + c) >> 1] =
                    cvt2(silu_f(cg[2]) * cu[2], silu_f(cg[3]) * cu[3]);
        }
}

// ================= down GEMM: BK=32, 2-stage, pure fp16, SPLIT-K x2 =================
// z = kz*9 + zz; kz selects K-half [kz*1024, kz*1024+1024); output -> g_P[kz*2 + routed]
#define DN_STG 18944
#define DN_SMEM_BYTES (2 * DN_STG)
#define DN_LDA 40
#define DN_LDB 136

__global__ void __launch_bounds__(256, 2)
gemm_down_all(const float* __restrict__ w_down) {
    const int BK = 32;
    const int K = F_DIM, N = D_DIM;     // K = full stride; loop covers half
    extern __shared__ __align__(16) char dsm[];

    int z = blockIdx.z;
    int kz = z / 9, zz = z - kz * 9;
    bool routed = (zz > 0);
    int e = zz - 1;
    int kbase = kz * (F_DIM / 2);       // 0 or 1024
    int seg_start = 0, seg_rows = T_TOK;
    const __half *A16, *Bp = nullptr;
    const float* Bf = nullptr;
    if (routed) {
        seg_start = g_offs[e]; seg_rows = g_offs[e + 1] - seg_start;
        A16 = g_H216;
        Bf = w_down + (size_t)e * F_DIM * D_DIM;
    } else {
        A16 = g_H16; Bp = g_sWd16;
    }
    int row0 = blockIdx.y * 128;
    if (row0 >= seg_rows) return;
    int col0 = blockIdx.x * 128;
    float* dst = g_P + (size_t)(kz * 2 + (routed ? 1 : 0)) * T_TOK * D_DIM;

    int tid = threadIdx.x, lane = tid & 31, wid = tid >> 5;
    int wm = wid & 3, wn = wid >> 2;

    auto pA = [&](int buf) { return (__half*)(dsm + buf * DN_STG); };
    auto pB = [&](int buf) { return (__half*)(dsm + buf * DN_STG + 10240); };

    int ar[2], ac[2]; const __half* ap[2];
#pragma unroll
    for (int i = 0; i < 2; i++) {
        int idx = i * 256 + tid;
        ar[i] = idx >> 2; ac[i] = (idx & 3) * 8;
        int rg = row0 + ar[i]; if (rg >= seg_rows) rg = 0;
        ap[i] = A16 + (size_t)(seg_start + rg) * K + kbase + ac[i];
    }
    int br[2], bc[2]; const __half* bps[2] = { nullptr, nullptr };
#pragma unroll
    for (int i = 0; i < 2; i++) {
        int idx = i * 256 + tid;
        br[i] = idx >> 4; bc[i] = (idx & 15) * 8;
        if (!routed) bps[i] = Bp + (size_t)(kbase + br[i]) * N + col0 + bc[i];
    }
    int bkr[4], bcc[4]; const float* bp[4] = { nullptr, nullptr, nullptr, nullptr };
#pragma unroll
    for (int i = 0; i < 4; i++) {
        int idx = i * 256 + tid;
        bkr[i] = idx >> 5; bcc[i] = (idx & 31) * 4;
        if (routed) bp[i] = Bf + (size_t)(kbase + bkr[i]) * N + col0 + bcc[i];
    }

    float acc[2][8][4] = {};

    auto stage_async = [&](int buf, int tile) {
        __half* sA = pA(buf);
#pragma unroll
        for (int i = 0; i < 2; i++)
            cpa16(sA + ar[i] * DN_LDA + ac[i], ap[i] + tile * BK);
        if (!routed) {
            __half* sB = pB(buf);
#pragma unroll
            for (int i = 0; i < 2; i++)
                cpa16(sB + br[i] * DN_LDB + bc[i], bps[i] + (size_t)tile * BK * N);
        }
        cpa_commit();
    };
    auto store_routedB = [&](int buf, const float4 bv[4]) {
        __half* sB = pB(buf);
#pragma unroll
        for (int i = 0; i < 4; i++) {
            int off = bkr[i] * DN_LDB + bcc[i];
            *(unsigned*)&sB[off]     = cvt2(bv[i].x, bv[i].y);
            *(unsigned*)&sB[off + 2] = cvt2(bv[i].z, bv[i].w);
        }
    };

    auto compute = [&](int buf) {
        const __half* sA = pA(buf);
        const __half* sB = pB(buf);
#pragma unroll
        for (int kh = 0; kh < 2; kh++) {
            unsigned a[2][4];
#pragma unroll
            for (int mt = 0; mt < 2; mt++) {
                int r = wm * 32 + mt * 16 + (lane & 15);
                int kk = kh * 16 + (lane >> 4) * 8;
                ldsm4(a[mt], sA + r * DN_LDA + kk);
            }
#pragma unroll
            for (int h = 0; h < 4; h++) {
                int krow = kh * 16 + (lane & 15);
                int nof = wn * 64 + h * 16 + (lane >> 4) * 8;
                unsigned bb[4];
                ldsm4t(bb, sB + krow * DN_LDB + nof);
#pragma unroll
                for (int mt = 0; mt < 2; mt++)
#pragma unroll
                    for (int nn = 0; nn < 2; nn++)
                        mma_f16(acc[mt][h * 2 + nn], a[mt], bb[2*nn], bb[2*nn+1]);
            }
        }
    };

    const int nC = (F_DIM / 2) / BK;   // 32
    stage_async(0, 0);
    if (routed) {
        float4 bv0[4] = { *(const float4*)bp[0], *(const float4*)bp[1],
                          *(const float4*)bp[2], *(const float4*)bp[3] };
        store_routedB(0, bv0);
    }
    cpa_wait_all();
    __syncthreads();

    for (int t = 0; t < nC; t++) {
        int buf = t & 1;
        bool more = (t + 1) < nC;
        float4 bv[4];
        if (more) {
            stage_async(buf ^ 1, t + 1);
            if (routed) {
#pragma unroll
                for (int i = 0; i < 4; i++)
                    bv[i] = *(const float4*)(bp[i] + (size_t)(t + 1) * BK * N);
            }
        }
        compute(buf);
        if (more) {
            if (routed) store_routedB(buf ^ 1, bv);
            cpa_wait_all();
        }
        __syncthreads();
    }

#pragma unroll
    for (int mt = 0; mt < 2; mt++) {
        int rb0 = row0 + wm * 32 + mt * 16 + (lane >> 2);
        int rb1 = rb0 + 8;
        int tok0 = -1, tok1 = -1;
        if (rb0 < seg_rows) tok0 = routed ? g_order[seg_start + rb0] : rb0;
        if (rb1 < seg_rows) tok1 = routed ? g_order[seg_start + rb1] : rb1;
#pragma unroll
        for (int nn = 0; nn < 8; nn++) {
            int c = col0 + wn * 64 + nn * 8 + (lane & 3) * 2;
            float* cc = acc[mt][nn];
            if (tok0 >= 0) { float2 v = { cc[0], cc[1] }; *(float2*)&dst[(size_t)tok0 * N + c] = v; }
            if (tok1 >= 0) { float2 v = { cc[2], cc[3] }; *(float2*)&dst[(size_t)tok1 * N + c] = v; }
        }
    }
}

// ---------------- final combine: out = P0+P1+P2+P3 ----------------
__global__ void add_kernel(float* __restrict__ out) {
    size_t i = (size_t)blockIdx.x * 256 + threadIdx.x;
    const size_t npl = (size_t)T_TOK * D_DIM / 4;
    float4 a = ((const float4*)g_P)[i];
    float4 b = ((const float4*)g_P)[i + npl];
    float4 c = ((const float4*)g_P)[i + 2 * npl];
    float4 d = ((const float4*)g_P)[i + 3 * npl];
    float4 v;
    v.x = (a.x + c.x) + (b.x + d.x);
    v.y = (a.y + c.y) + (b.y + d.y);
    v.z = (a.z + c.z) + (b.z + d.z);
    v.w = (a.w + c.w) + (b.w + d.w);
    ((float4*)out)[i] = v;
}

extern "C" void kernel_launch(void* const* d_in, const int* in_sizes, int n_in,
                              void* d_out, int out_size) {
    const float* hidden   = (const float*)d_in[0];
    const float* router_w = (const float*)d_in[1];
    const float* w_gate   = (const float*)d_in[2];
    const float* w_up     = (const float*)d_in[3];
    const float* w_down   = (const float*)d_in[4];
    const float* ws_gate  = (const float*)d_in[5];
    const float* ws_up    = (const float*)d_in[6];
    const float* ws_down  = (const float*)d_in[7];
    float* out = (float*)d_out;

    cudaFuncSetAttribute(gemm_gateup_all, cudaFuncAttributeMaxDynamicSharedMemorySize, GU_SMEM_BYTES);
    cudaFuncSetAttribute(gemm_down_all,   cudaFuncAttributeMaxDynamicSharedMemorySize, DN_SMEM_BYTES);

    conv_shared<<<512, 256>>>(ws_gate, ws_up, ws_down);
    router_kernel<<<T_TOK, 256>>>(hidden, router_w);
    rank_kernel<<<T_TOK / 256, 256>>>();
    scatter_convert<<<T_TOK, 256>>>(hidden);

    dim3 gridGU(F_DIM / 64, T_TOK / 128, NE + 1);
    gemm_gateup_all<<<gridGU, 256, GU_SMEM_BYTES>>>(w_gate, w_up);
    dim3 gridDN(D_DIM / 128, T_TOK / 128, 2 * (NE + 1));
    gemm_down_all<<<gridDN, 256, DN_SMEM_BYTES>>>(w_down);
    add_kernel<<<(T_TOK * D_DIM / 4) / 256, 256>>>(out);

    (void)in_sizes; (void)n_in; (void)out_size;
}